// round 13
// baseline (speedup 1.0000x reference)
#include <cuda_runtime.h>
#include <cuda_fp16.h>
#include <math.h>
#include <stdint.h>

// ---------------------------------------------------------------------------
// EncoderBlock: B=16, N=1024, DIM=768, HEADS=12, HEAD_DIM=64, HIDDEN=3072
// T = 16384 tokens. All matmuls: mma.sync m16n8k16 fp16 (fp32 accumulate).
// R13: attention softmax on exp2 (log2e folded into Q prescale) + hoisted
// ldmatrix bases. GEMMs unchanged (measured best, ~85% of fallback floor).
// ---------------------------------------------------------------------------

#define T_TOK 16384

// Scratch (device globals: allocation-guard safe)
__device__ __half g_xn1 [T_TOK * 768];
__device__ __half g_qkv [T_TOK * 2304];
__device__ __half g_ctx [T_TOK * 768];
__device__ float  g_x2  [T_TOK * 768];
__device__ __half g_ffin[T_TOK * 768];
__device__ __half g_hid [T_TOK * 3072];
__device__ float  g_x3  [T_TOK * 768];
// transposed fp16 weights Wt[N,K]
__device__ __half g_wq  [2304 * 768];
__device__ __half g_wp  [768 * 768];
__device__ __half g_w1  [3072 * 768];
__device__ __half g_w2  [768 * 3072];

// ---------------------------------------------------------------------------
// helpers
// ---------------------------------------------------------------------------
__device__ __forceinline__ void mma16(float* c, const unsigned* a, const unsigned* b) {
    asm volatile(
        "mma.sync.aligned.m16n8k16.row.col.f32.f16.f16.f32 "
        "{%0,%1,%2,%3}, {%4,%5,%6,%7}, {%8,%9}, {%0,%1,%2,%3};\n"
        : "+f"(c[0]), "+f"(c[1]), "+f"(c[2]), "+f"(c[3])
        : "r"(a[0]), "r"(a[1]), "r"(a[2]), "r"(a[3]), "r"(b[0]), "r"(b[1]));
}

__device__ __forceinline__ void ldsm4(unsigned& r0, unsigned& r1, unsigned& r2,
                                      unsigned& r3, uint32_t addr) {
    asm volatile("ldmatrix.sync.aligned.m8n8.x4.shared.b16 {%0,%1,%2,%3}, [%4];"
                 : "=r"(r0), "=r"(r1), "=r"(r2), "=r"(r3) : "r"(addr));
}

__device__ __forceinline__ void ldsm4t(unsigned& r0, unsigned& r1, unsigned& r2,
                                       unsigned& r3, uint32_t addr) {
    asm volatile("ldmatrix.sync.aligned.m8n8.x4.trans.shared.b16 {%0,%1,%2,%3}, [%4];"
                 : "=r"(r0), "=r"(r1), "=r"(r2), "=r"(r3) : "r"(addr));
}

__device__ __forceinline__ void cp16(__half* dst, const __half* src) {
    unsigned d = (unsigned)__cvta_generic_to_shared(dst);
    asm volatile("cp.async.cg.shared.global [%0], [%1], 16;\n" :: "r"(d), "l"(src));
}
__device__ __forceinline__ void cp_commit() { asm volatile("cp.async.commit_group;\n"); }
template <int N>
__device__ __forceinline__ void cp_wait() { asm volatile("cp.async.wait_group %0;\n" :: "n"(N)); }

__device__ __forceinline__ unsigned pack2(float x, float y) {
    __half2 h = __floats2half2_rn(x, y);
    return *(unsigned*)&h;
}

// ---------------------------------------------------------------------------
// fused weight transpose + fp16 round: 4x W[K,N] -> Wt[N,K] half, one launch
// ---------------------------------------------------------------------------
__global__ __launch_bounds__(256) void transpose4(
    const float* __restrict__ w0, __half* __restrict__ o0,
    const float* __restrict__ w1, __half* __restrict__ o1,
    const float* __restrict__ w2, __half* __restrict__ o2,
    const float* __restrict__ w3, __half* __restrict__ o3)
{
    int bid = blockIdx.x;
    const float* in; __half* out; int K, N, t;
    if (bid < 1728)      { in = w0; out = o0; K = 768;  N = 2304; t = bid; }
    else if (bid < 2304) { in = w1; out = o1; K = 768;  N = 768;  t = bid - 1728; }
    else if (bid < 4608) { in = w2; out = o2; K = 768;  N = 3072; t = bid - 2304; }
    else                 { in = w3; out = o3; K = 3072; N = 768;  t = bid - 4608; }
    int xt = N / 32;
    int n0 = (t % xt) * 32, k0 = (t / xt) * 32;

    __shared__ float s[32][33];
    int tx = threadIdx.x & 31, ty = threadIdx.x >> 5;
#pragma unroll
    for (int j = 0; j < 4; j++)
        s[ty + 8 * j][tx] = in[(size_t)(k0 + ty + 8 * j) * N + n0 + tx];
    __syncthreads();
#pragma unroll
    for (int j = 0; j < 4; j++)
        out[(size_t)(n0 + ty + 8 * j) * K + k0 + tx] = __float2half_rn(s[tx][ty + 8 * j]);
}

// ---------------------------------------------------------------------------
// LayerNorm over 768. OUTH: write half (GEMM A operand) else float.
// ---------------------------------------------------------------------------
template <int OUTH>
__global__ __launch_bounds__(256) void ln_kernel(
    const float* __restrict__ in, const float* __restrict__ g,
    const float* __restrict__ b, void* __restrict__ outv)
{
    int row = blockIdx.x;
    const float* p = in + (size_t)row * 768;
    float v[3];
    float s = 0.f, ss = 0.f;
#pragma unroll
    for (int i = 0; i < 3; i++) {
        v[i] = p[threadIdx.x + i * 256];
        s += v[i]; ss += v[i] * v[i];
    }
#pragma unroll
    for (int o = 16; o > 0; o >>= 1) {
        s  += __shfl_xor_sync(0xffffffffu, s,  o);
        ss += __shfl_xor_sync(0xffffffffu, ss, o);
    }
    __shared__ float rs[8], rss[8];
    int w = threadIdx.x >> 5, lane = threadIdx.x & 31;
    if (lane == 0) { rs[w] = s; rss[w] = ss; }
    __syncthreads();
    s = 0.f; ss = 0.f;
#pragma unroll
    for (int i = 0; i < 8; i++) { s += rs[i]; ss += rss[i]; }
    float mean = s * (1.0f / 768.0f);
    float var  = ss * (1.0f / 768.0f) - mean * mean;
    float rstd = rsqrtf(var + 1e-5f);
#pragma unroll
    for (int i = 0; i < 3; i++) {
        int c = threadIdx.x + i * 256;
        float r = (v[i] - mean) * rstd * g[c] + b[c];
        if (OUTH) ((__half*)outv)[(size_t)row * 768 + c] = __float2half_rn(r);
        else      ((float*)outv)[(size_t)row * 768 + c] = r;
    }
}

// ---------------------------------------------------------------------------
// fp16 mma GEMM (R8 shape): 3-stage cp.async pipeline, frag double-buffer.
// C[M,N] = A[M,K] @ W[K,N] + bias; W transposed Wt[N,K].
// 128x256x32 CTA tile, 256 threads (8 warps 2x4), warp tile 64x64.
//   EPI=0 none | EPI=1 exact GELU | EPI=2 += res
//   OUTH: out half else float. RESH: residual half else float.
// ---------------------------------------------------------------------------
#define SM_S 40
#define GA_BUF (128 * SM_S)
#define GB_BUF (256 * SM_S)
#define GEMM_SMEM (3 * (GA_BUF + GB_BUF) * 2)

template <int EPI, int OUTH, int RESH>
__global__ __launch_bounds__(256, 1) void gemm_f16(
    const __half* __restrict__ A, const __half* __restrict__ Bt,
    const float* __restrict__ bias, const void* __restrict__ resv,
    void* __restrict__ Cv, int M, int N, int K)
{
    extern __shared__ __half smh[];
    __half* As = smh;                          // [3][128][SM_S]
    __half* Bs = smh + 3 * GA_BUF;             // [3][256][SM_S]

    int tid = threadIdx.x;
    int warp = tid >> 5, lane = tid & 31;
    int g = lane >> 2, t = lane & 3;
    int wm = (warp & 1) * 64, wn = (warp >> 1) * 64;
    int bm = blockIdx.y * 128, bn = blockIdx.x * 256;

    float acc[4][8][4];
#pragma unroll
    for (int i = 0; i < 4; i++)
#pragma unroll
        for (int j = 0; j < 8; j++)
#pragma unroll
            for (int q = 0; q < 4; q++) acc[i][j][q] = 0.f;

    const __half* Agb = A + (size_t)bm * K;
    const __half* Bgb = Bt + (size_t)bn * K;
    int ntile = K >> 5;

    // prologue: tiles 0, 1 -> stages 0, 1
#pragma unroll
    for (int pt = 0; pt < 2; pt++) {
        __half* Ab = As + pt * GA_BUF;
        __half* Bb = Bs + pt * GB_BUF;
        int k0 = pt * 32;
#pragma unroll
        for (int i = 0; i < 2; i++) {
            int idx = tid + i * 256; int r = idx >> 2, c = (idx & 3) * 8;
            cp16(&Ab[r * SM_S + c], Agb + (size_t)r * K + k0 + c);
        }
#pragma unroll
        for (int i = 0; i < 4; i++) {
            int idx = tid + i * 256; int r = idx >> 2, c = (idx & 3) * 8;
            cp16(&Bb[r * SM_S + c], Bgb + (size_t)r * K + k0 + c);
        }
        cp_commit();
    }

    for (int tt = 0; tt < ntile; tt++) {
        if (tt + 2 < ntile) {
            int st2 = (tt + 2) % 3;
            int k0 = (tt + 2) * 32;
            __half* Ab = As + st2 * GA_BUF;
            __half* Bb = Bs + st2 * GB_BUF;
#pragma unroll
            for (int i = 0; i < 2; i++) {
                int idx = tid + i * 256; int r = idx >> 2, c = (idx & 3) * 8;
                cp16(&Ab[r * SM_S + c], Agb + (size_t)r * K + k0 + c);
            }
#pragma unroll
            for (int i = 0; i < 4; i++) {
                int idx = tid + i * 256; int r = idx >> 2, c = (idx & 3) * 8;
                cp16(&Bb[r * SM_S + c], Bgb + (size_t)r * K + k0 + c);
            }
            cp_commit();
            cp_wait<2>();
        } else if (tt + 1 < ntile) {
            cp_wait<1>();
        } else {
            cp_wait<0>();
        }
        __syncthreads();

        int st = tt % 3;
        const __half* Abase = As + st * GA_BUF + (wm + g) * SM_S + 2 * t;
        const __half* Bbase = Bs + st * GB_BUF + (wn + g) * SM_S + 2 * t;

        unsigned a[2][4][4], b[2][8][2];
#pragma unroll
        for (int mt = 0; mt < 4; mt++) {
            const __half* p = Abase + mt * 16 * SM_S;
            a[0][mt][0] = *(const unsigned*)(p);
            a[0][mt][1] = *(const unsigned*)(p + 8 * SM_S);
            a[0][mt][2] = *(const unsigned*)(p + 8);
            a[0][mt][3] = *(const unsigned*)(p + 8 * SM_S + 8);
        }
#pragma unroll
        for (int nt = 0; nt < 8; nt++) {
            const __half* p = Bbase + nt * 8 * SM_S;
            b[0][nt][0] = *(const unsigned*)(p);
            b[0][nt][1] = *(const unsigned*)(p + 8);
        }
#pragma unroll
        for (int s = 0; s < 2; s++) {
            if (s == 0) {
#pragma unroll
                for (int mt = 0; mt < 4; mt++) {
                    const __half* p = Abase + mt * 16 * SM_S + 16;
                    a[1][mt][0] = *(const unsigned*)(p);
                    a[1][mt][1] = *(const unsigned*)(p + 8 * SM_S);
                    a[1][mt][2] = *(const unsigned*)(p + 8);
                    a[1][mt][3] = *(const unsigned*)(p + 8 * SM_S + 8);
                }
#pragma unroll
                for (int nt = 0; nt < 8; nt++) {
                    const __half* p = Bbase + nt * 8 * SM_S + 16;
                    b[1][nt][0] = *(const unsigned*)(p);
                    b[1][nt][1] = *(const unsigned*)(p + 8);
                }
            }
#pragma unroll
            for (int mt = 0; mt < 4; mt++)
#pragma unroll
                for (int nt = 0; nt < 8; nt++)
                    mma16(acc[mt][nt], a[s][mt], b[s][nt]);
        }
        __syncthreads();
    }

    // epilogue
#pragma unroll
    for (int mt = 0; mt < 4; mt++) {
        int r0 = bm + wm + mt * 16 + g;
        int r1 = r0 + 8;
#pragma unroll
        for (int nt = 0; nt < 8; nt++) {
            int col = bn + wn + nt * 8 + 2 * t;
            float b0 = bias[col], b1 = bias[col + 1];
            float v0 = acc[mt][nt][0] + b0, v1 = acc[mt][nt][1] + b1;
            float v2 = acc[mt][nt][2] + b0, v3 = acc[mt][nt][3] + b1;
            if (EPI == 1) {
                v0 = 0.5f * v0 * (1.0f + erff(v0 * 0.70710678118654752f));
                v1 = 0.5f * v1 * (1.0f + erff(v1 * 0.70710678118654752f));
                v2 = 0.5f * v2 * (1.0f + erff(v2 * 0.70710678118654752f));
                v3 = 0.5f * v3 * (1.0f + erff(v3 * 0.70710678118654752f));
            }
            if (EPI == 2) {
                if (RESH) {
                    const __half* rh = (const __half*)resv;
                    float2 ra = __half22float2(*(const __half2*)(rh + (size_t)r0 * N + col));
                    float2 rb = __half22float2(*(const __half2*)(rh + (size_t)r1 * N + col));
                    v0 += ra.x; v1 += ra.y; v2 += rb.x; v3 += rb.y;
                } else {
                    const float* rf = (const float*)resv;
                    float2 ra = *(const float2*)(rf + (size_t)r0 * N + col);
                    float2 rb = *(const float2*)(rf + (size_t)r1 * N + col);
                    v0 += ra.x; v1 += ra.y; v2 += rb.x; v3 += rb.y;
                }
            }
            if (OUTH) {
                __half* Ch = (__half*)Cv;
                *(__half2*)(Ch + (size_t)r0 * N + col) = __floats2half2_rn(v0, v1);
                *(__half2*)(Ch + (size_t)r1 * N + col) = __floats2half2_rn(v2, v3);
            } else {
                float* Cf = (float*)Cv;
                *(float2*)(Cf + (size_t)r0 * N + col) = make_float2(v0, v1);
                *(float2*)(Cf + (size_t)r1 * N + col) = make_float2(v2, v3);
            }
        }
    }
}

// ---------------------------------------------------------------------------
// Flash attention fp16 v4. Br=128, Bc=64, 128 threads (4 warps, 32 q-rows).
// Softmax in log2 domain: Q prescaled by 0.125*log2(e); exp2f only (no FMUL).
// P in registers (C-frag == A-frag layout). Hoisted ldmatrix bases.
// cp.async double-buffered K/V, 1 syncthreads per iteration.
// qkv half [T, 2304]: Q +0, K +768, V +1536 (head h: +h*64).
// ---------------------------------------------------------------------------
#define AT_S 72
#define ATT_SMEM ((128 + 4 * 64) * AT_S * 2)

__global__ __launch_bounds__(128, 2) void attn_f16(
    const __half* __restrict__ qkv, __half* __restrict__ ctx)
{
    extern __shared__ __half smh[];
    __half* Qs = smh;                         // Q [128][AT_S]
    __half* KV = smh + 128 * AT_S;            // [2 stages][K 64 | V 64][AT_S]

    int tid = threadIdx.x, warp = tid >> 5, lane = tid & 31;
    int g = lane >> 2, t = lane & 3;
    int bh = blockIdx.y, b = bh / 12, h = bh % 12;
    size_t base = (size_t)b * 1024 * 2304 + h * 64;
    int q0 = blockIdx.x * 128;

    // issue K/V tile 0 -> stage 0 first (hide latency under Q load)
    {
        __half* kb = KV;
        __half* vb = KV + 64 * AT_S;
        const __half* kp = qkv + base + 768;
#pragma unroll
        for (int i = 0; i < 4; i++) {
            int idx = tid + i * 128;
            int r = idx >> 3, c = (idx & 7) * 8;
            cp16(&kb[r * AT_S + c], kp + (size_t)r * 2304 + c);
            cp16(&vb[r * AT_S + c], kp + (size_t)r * 2304 + 768 + c);
        }
        cp_commit();
    }

    // load Q [128 x 64], scaled by 0.125*log2(e) -> scores in log2 domain
    __half2 s2 = __floats2half2_rn(0.18033688011112042f, 0.18033688011112042f);
#pragma unroll
    for (int i = 0; i < 8; i++) {
        int idx = tid + i * 128;
        int r = idx >> 3, c = (idx & 7) * 8;
        uint4 u = *(const uint4*)(qkv + base + (size_t)(q0 + r) * 2304 + c);
        __half2* hp = (__half2*)&u;
        hp[0] = __hmul2(hp[0], s2); hp[1] = __hmul2(hp[1], s2);
        hp[2] = __hmul2(hp[2], s2); hp[3] = __hmul2(hp[3], s2);
        *(uint4*)&Qs[r * AT_S + c] = u;
    }
    __syncthreads();

    // Q fragments in regs for whole kernel: 2 m-frags (rows warp*32 + mf*16)
    unsigned qa[2][4][4];
#pragma unroll
    for (int mf = 0; mf < 2; mf++) {
        const __half* p0 = &Qs[(warp * 32 + mf * 16 + g) * AT_S + 2 * t];
#pragma unroll
        for (int s = 0; s < 4; s++) {
            qa[mf][s][0] = *(const unsigned*)(p0 + 16 * s);
            qa[mf][s][1] = *(const unsigned*)(p0 + 16 * s + 8 * AT_S);
            qa[mf][s][2] = *(const unsigned*)(p0 + 16 * s + 8);
            qa[mf][s][3] = *(const unsigned*)(p0 + 16 * s + 8 * AT_S + 8);
        }
    }

    float o[2][8][4];
#pragma unroll
    for (int mf = 0; mf < 2; mf++)
#pragma unroll
        for (int i = 0; i < 8; i++)
#pragma unroll
            for (int j = 0; j < 4; j++) o[mf][i][j] = 0.f;
    float mrow[2][2] = {{-1e30f, -1e30f}, {-1e30f, -1e30f}};
    float lrow[2][2] = {{0.f, 0.f}, {0.f, 0.f}};

    // ldmatrix lane maps + hoisted per-stage base addresses
    int mid = lane >> 3, row8 = lane & 7;
    int bk_off = ((mid >> 1) ? 8 : 0) + row8;   // K B-frag key offset
    int bc_off = (mid & 1) * 8;                 // K B-frag k-col offset
    int lm_row = (mid & 1) * 8 + row8;          // V trans map
    int lm_col = (mid >> 1) * 8;
    uint32_t kv_smem = (uint32_t)__cvta_generic_to_shared(KV);
    uint32_t kbase[2], vbase[2];
#pragma unroll
    for (int bfi = 0; bfi < 2; bfi++) {
        uint32_t ks = kv_smem + bfi * (2 * 64 * AT_S) * 2;
        kbase[bfi] = ks + (bk_off * AT_S + bc_off) * 2;
        vbase[bfi] = ks + 64 * AT_S * 2 + (lm_row * AT_S + lm_col) * 2;
    }

    for (int kt = 0; kt < 16; kt++) {
        cp_wait<0>();
        __syncthreads();

        // issue tile kt+1
        if (kt + 1 < 16) {
            int nb = (kt + 1) & 1;
            __half* kb = KV + nb * (2 * 64 * AT_S);
            __half* vb = kb + 64 * AT_S;
            const __half* kp = qkv + base + (size_t)((kt + 1) * 64) * 2304 + 768;
#pragma unroll
            for (int i = 0; i < 4; i++) {
                int idx = tid + i * 128;
                int r = idx >> 3, c = (idx & 7) * 8;
                cp16(&kb[r * AT_S + c], kp + (size_t)r * 2304 + c);
                cp16(&vb[r * AT_S + c], kp + (size_t)r * 2304 + 768 + c);
            }
            cp_commit();
        }

        int buf = kt & 1;
        uint32_t kb0 = kbase[buf], vb0 = vbase[buf];

        // S = Q K^T (log2-domain scores); K B-frags shared across both m-frags
        float sc[2][8][4];
#pragma unroll
        for (int mf = 0; mf < 2; mf++)
#pragma unroll
            for (int i = 0; i < 8; i++)
#pragma unroll
                for (int j = 0; j < 4; j++) sc[mf][i][j] = 0.f;
#pragma unroll
        for (int s = 0; s < 4; s++) {
#pragma unroll
            for (int np = 0; np < 4; np++) {
                uint32_t addr = kb0 + (np * 16 * AT_S + 16 * s) * 2;
                unsigned r0, r1, r2, r3;
                ldsm4(r0, r1, r2, r3, addr);
                unsigned b0[2] = {r0, r1}, b1[2] = {r2, r3};
#pragma unroll
                for (int mf = 0; mf < 2; mf++) {
                    mma16(sc[mf][np * 2 + 0], qa[mf][s], b0);
                    mma16(sc[mf][np * 2 + 1], qa[mf][s], b1);
                }
            }
        }

        // online softmax per m-frag (log2 domain, exp2 only); sc <- P
#pragma unroll
        for (int mf = 0; mf < 2; mf++) {
            float mx0 = -1e30f, mx1 = -1e30f;
#pragma unroll
            for (int nt = 0; nt < 8; nt++) {
                mx0 = fmaxf(mx0, fmaxf(sc[mf][nt][0], sc[mf][nt][1]));
                mx1 = fmaxf(mx1, fmaxf(sc[mf][nt][2], sc[mf][nt][3]));
            }
            mx0 = fmaxf(mx0, __shfl_xor_sync(0xffffffffu, mx0, 1));
            mx0 = fmaxf(mx0, __shfl_xor_sync(0xffffffffu, mx0, 2));
            mx1 = fmaxf(mx1, __shfl_xor_sync(0xffffffffu, mx1, 1));
            mx1 = fmaxf(mx1, __shfl_xor_sync(0xffffffffu, mx1, 2));
            float nm0 = fmaxf(mrow[mf][0], mx0), nm1 = fmaxf(mrow[mf][1], mx1);
            float al0 = exp2f(mrow[mf][0] - nm0), al1 = exp2f(mrow[mf][1] - nm1);
            float ps0 = 0.f, ps1 = 0.f;
#pragma unroll
            for (int nt = 0; nt < 8; nt++) {
                float p0 = exp2f(sc[mf][nt][0] - nm0);
                float p1 = exp2f(sc[mf][nt][1] - nm0);
                float p2 = exp2f(sc[mf][nt][2] - nm1);
                float p3 = exp2f(sc[mf][nt][3] - nm1);
                ps0 += p0 + p1; ps1 += p2 + p3;
                sc[mf][nt][0] = p0; sc[mf][nt][1] = p1;
                sc[mf][nt][2] = p2; sc[mf][nt][3] = p3;
            }
            ps0 += __shfl_xor_sync(0xffffffffu, ps0, 1);
            ps0 += __shfl_xor_sync(0xffffffffu, ps0, 2);
            ps1 += __shfl_xor_sync(0xffffffffu, ps1, 1);
            ps1 += __shfl_xor_sync(0xffffffffu, ps1, 2);
            lrow[mf][0] = lrow[mf][0] * al0 + ps0;
            lrow[mf][1] = lrow[mf][1] * al1 + ps1;
            mrow[mf][0] = nm0; mrow[mf][1] = nm1;
#pragma unroll
            for (int nt = 0; nt < 8; nt++) {
                o[mf][nt][0] *= al0; o[mf][nt][1] *= al0;
                o[mf][nt][2] *= al1; o[mf][nt][3] *= al1;
            }
        }

        // O += P @ V ; P A-frags from registers, V via ldmatrix.x4.trans
#pragma unroll
        for (int s = 0; s < 4; s++) {
            unsigned pa[2][4];
#pragma unroll
            for (int mf = 0; mf < 2; mf++) {
                pa[mf][0] = pack2(sc[mf][2 * s][0], sc[mf][2 * s][1]);
                pa[mf][1] = pack2(sc[mf][2 * s][2], sc[mf][2 * s][3]);
                pa[mf][2] = pack2(sc[mf][2 * s + 1][0], sc[mf][2 * s + 1][1]);
                pa[mf][3] = pack2(sc[mf][2 * s + 1][2], sc[mf][2 * s + 1][3]);
            }
#pragma unroll
            for (int nt2 = 0; nt2 < 4; nt2++) {
                uint32_t addr = vb0 + (16 * s * AT_S + nt2 * 16) * 2;
                unsigned r0, r1, r2, r3;
                ldsm4t(r0, r1, r2, r3, addr);
                unsigned b0[2] = {r0, r1}, b1[2] = {r2, r3};
#pragma unroll
                for (int mf = 0; mf < 2; mf++) {
                    mma16(o[mf][nt2 * 2 + 0], pa[mf], b0);
                    mma16(o[mf][nt2 * 2 + 1], pa[mf], b1);
                }
            }
        }
        // no trailing sync: next iteration's barrier covers buffer reuse
    }

    __half* outb = ctx + (size_t)(b * 1024) * 768 + h * 64;
#pragma unroll
    for (int mf = 0; mf < 2; mf++) {
        float i0 = 1.0f / lrow[mf][0], i1 = 1.0f / lrow[mf][1];
        int row0 = q0 + warp * 32 + mf * 16 + g;
#pragma unroll
        for (int nt = 0; nt < 8; nt++) {
            int col = nt * 8 + 2 * t;
            *(__half2*)(outb + (size_t)row0 * 768 + col) =
                __floats2half2_rn(o[mf][nt][0] * i0, o[mf][nt][1] * i0);
            *(__half2*)(outb + (size_t)(row0 + 8) * 768 + col) =
                __floats2half2_rn(o[mf][nt][2] * i1, o[mf][nt][3] * i1);
        }
    }
}

// ---------------------------------------------------------------------------
// Host launch (graph-capturable)
// ---------------------------------------------------------------------------
extern "C" void kernel_launch(void* const* d_in, const int* in_sizes, int n_in,
                              void* d_out, int out_size)
{
    const float* x      = (const float*)d_in[0];
    const float* ln1_g  = (const float*)d_in[1];
    const float* ln1_b  = (const float*)d_in[2];
    const float* qkv_w  = (const float*)d_in[3];
    const float* qkv_b  = (const float*)d_in[4];
    const float* proj_w = (const float*)d_in[5];
    const float* proj_b = (const float*)d_in[6];
    const float* ln2_g  = (const float*)d_in[7];
    const float* ln2_b  = (const float*)d_in[8];
    const float* fc1_w  = (const float*)d_in[9];
    const float* fc1_b  = (const float*)d_in[10];
    const float* fc2_w  = (const float*)d_in[11];
    const float* fc2_b  = (const float*)d_in[12];
    const float* ln3_g  = (const float*)d_in[13];
    const float* ln3_b  = (const float*)d_in[14];
    float* out = (float*)d_out;

    __half *xn1, *qkv, *ctx, *ffin, *hid, *wq, *wp, *w1, *w2;
    float *x2, *x3;
    cudaGetSymbolAddress((void**)&xn1,  g_xn1);
    cudaGetSymbolAddress((void**)&qkv,  g_qkv);
    cudaGetSymbolAddress((void**)&ctx,  g_ctx);
    cudaGetSymbolAddress((void**)&x2,   g_x2);
    cudaGetSymbolAddress((void**)&ffin, g_ffin);
    cudaGetSymbolAddress((void**)&hid,  g_hid);
    cudaGetSymbolAddress((void**)&x3,   g_x3);
    cudaGetSymbolAddress((void**)&wq,   g_wq);
    cudaGetSymbolAddress((void**)&wp,   g_wp);
    cudaGetSymbolAddress((void**)&w1,   g_w1);
    cudaGetSymbolAddress((void**)&w2,   g_w2);

    cudaFuncSetAttribute(gemm_f16<0,1,0>, cudaFuncAttributeMaxDynamicSharedMemorySize, GEMM_SMEM);
    cudaFuncSetAttribute(gemm_f16<1,1,0>, cudaFuncAttributeMaxDynamicSharedMemorySize, GEMM_SMEM);
    cudaFuncSetAttribute(gemm_f16<2,0,0>, cudaFuncAttributeMaxDynamicSharedMemorySize, GEMM_SMEM);
    cudaFuncSetAttribute(gemm_f16<2,0,1>, cudaFuncAttributeMaxDynamicSharedMemorySize, GEMM_SMEM);
    cudaFuncSetAttribute(attn_f16, cudaFuncAttributeMaxDynamicSharedMemorySize, ATT_SMEM);

    const int T = T_TOK;

    // fused weight transpose + fp16 round (one launch)
    transpose4<<<6912, 256>>>(qkv_w, wq, proj_w, wp, fc1_w, w1, fc2_w, w2);

    // 1) xn1 = LN1(x) [half]
    ln_kernel<1><<<T, 256>>>(x, ln1_g, ln1_b, xn1);
    // 2) qkv = xn1 @ qkv_w + qkv_b [half]  (128x256 tiles)
    gemm_f16<0,1,0><<<dim3(9, 128), 256, GEMM_SMEM>>>(xn1, wq, qkv_b, nullptr, qkv, T, 2304, 768);
    // 3) ctx = attention(qkv) [half]
    attn_f16<<<dim3(8, 192), 128, ATT_SMEM>>>(qkv, ctx);
    // 4) x2 = x + ctx @ proj_w + proj_b [float]
    gemm_f16<2,0,0><<<dim3(3, 128), 256, GEMM_SMEM>>>(ctx, wp, proj_b, x, x2, T, 768, 768);
    // 5) ffin = LN2(x2) [half]
    ln_kernel<1><<<T, 256>>>(x2, ln2_g, ln2_b, ffin);
    // 6) hid = gelu(ffin @ fc1_w + fc1_b) [half]
    gemm_f16<1,1,0><<<dim3(12, 128), 256, GEMM_SMEM>>>(ffin, w1, fc1_b, nullptr, hid, T, 3072, 768);
    // 7) x3 = ffin + hid @ fc2_w + fc2_b [float] (residual from NORMALIZED tensor)
    gemm_f16<2,0,1><<<dim3(3, 128), 256, GEMM_SMEM>>>(hid, w2, fc2_b, ffin, x3, T, 768, 3072);
    // 8) out = LN3(x3)
    ln_kernel<0><<<T, 256>>>(x3, ln3_g, ln3_b, out);
}

// round 14
// speedup vs baseline: 1.0220x; 1.0220x over previous
#include <cuda_runtime.h>
#include <cuda_fp16.h>
#include <math.h>
#include <stdint.h>

// ---------------------------------------------------------------------------
// EncoderBlock: B=16, N=1024, DIM=768, HEADS=12, HEAD_DIM=64, HIDDEN=3072
// T = 16384 tokens. All matmuls: mma.sync m16n8k16 fp16 (fp32 accumulate).
// R14: R13 softmax-in-log2-domain, but exp2 via ex2.approx.ftz PTX (single
// MUFU — libdevice exp2f was the accurate slow path and caused R13's
// regression). GEMMs unchanged.
// ---------------------------------------------------------------------------

#define T_TOK 16384

// Scratch (device globals: allocation-guard safe)
__device__ __half g_xn1 [T_TOK * 768];
__device__ __half g_qkv [T_TOK * 2304];
__device__ __half g_ctx [T_TOK * 768];
__device__ float  g_x2  [T_TOK * 768];
__device__ __half g_ffin[T_TOK * 768];
__device__ __half g_hid [T_TOK * 3072];
__device__ float  g_x3  [T_TOK * 768];
// transposed fp16 weights Wt[N,K]
__device__ __half g_wq  [2304 * 768];
__device__ __half g_wp  [768 * 768];
__device__ __half g_w1  [3072 * 768];
__device__ __half g_w2  [768 * 3072];

// ---------------------------------------------------------------------------
// helpers
// ---------------------------------------------------------------------------
__device__ __forceinline__ void mma16(float* c, const unsigned* a, const unsigned* b) {
    asm volatile(
        "mma.sync.aligned.m16n8k16.row.col.f32.f16.f16.f32 "
        "{%0,%1,%2,%3}, {%4,%5,%6,%7}, {%8,%9}, {%0,%1,%2,%3};\n"
        : "+f"(c[0]), "+f"(c[1]), "+f"(c[2]), "+f"(c[3])
        : "r"(a[0]), "r"(a[1]), "r"(a[2]), "r"(a[3]), "r"(b[0]), "r"(b[1]));
}

__device__ __forceinline__ void ldsm4(unsigned& r0, unsigned& r1, unsigned& r2,
                                      unsigned& r3, uint32_t addr) {
    asm volatile("ldmatrix.sync.aligned.m8n8.x4.shared.b16 {%0,%1,%2,%3}, [%4];"
                 : "=r"(r0), "=r"(r1), "=r"(r2), "=r"(r3) : "r"(addr));
}

__device__ __forceinline__ void ldsm4t(unsigned& r0, unsigned& r1, unsigned& r2,
                                       unsigned& r3, uint32_t addr) {
    asm volatile("ldmatrix.sync.aligned.m8n8.x4.trans.shared.b16 {%0,%1,%2,%3}, [%4];"
                 : "=r"(r0), "=r"(r1), "=r"(r2), "=r"(r3) : "r"(addr));
}

__device__ __forceinline__ void cp16(__half* dst, const __half* src) {
    unsigned d = (unsigned)__cvta_generic_to_shared(dst);
    asm volatile("cp.async.cg.shared.global [%0], [%1], 16;\n" :: "r"(d), "l"(src));
}
__device__ __forceinline__ void cp_commit() { asm volatile("cp.async.commit_group;\n"); }
template <int N>
__device__ __forceinline__ void cp_wait() { asm volatile("cp.async.wait_group %0;\n" :: "n"(N)); }

__device__ __forceinline__ unsigned pack2(float x, float y) {
    __half2 h = __floats2half2_rn(x, y);
    return *(unsigned*)&h;
}

// single-MUFU exp2 (hardware EX2 approx; accurate to ~2^-22 on our range)
__device__ __forceinline__ float ex2(float x) {
    float y;
    asm("ex2.approx.ftz.f32 %0, %1;" : "=f"(y) : "f"(x));
    return y;
}

// ---------------------------------------------------------------------------
// fused weight transpose + fp16 round: 4x W[K,N] -> Wt[N,K] half, one launch
// ---------------------------------------------------------------------------
__global__ __launch_bounds__(256) void transpose4(
    const float* __restrict__ w0, __half* __restrict__ o0,
    const float* __restrict__ w1, __half* __restrict__ o1,
    const float* __restrict__ w2, __half* __restrict__ o2,
    const float* __restrict__ w3, __half* __restrict__ o3)
{
    int bid = blockIdx.x;
    const float* in; __half* out; int K, N, t;
    if (bid < 1728)      { in = w0; out = o0; K = 768;  N = 2304; t = bid; }
    else if (bid < 2304) { in = w1; out = o1; K = 768;  N = 768;  t = bid - 1728; }
    else if (bid < 4608) { in = w2; out = o2; K = 768;  N = 3072; t = bid - 2304; }
    else                 { in = w3; out = o3; K = 3072; N = 768;  t = bid - 4608; }
    int xt = N / 32;
    int n0 = (t % xt) * 32, k0 = (t / xt) * 32;

    __shared__ float s[32][33];
    int tx = threadIdx.x & 31, ty = threadIdx.x >> 5;
#pragma unroll
    for (int j = 0; j < 4; j++)
        s[ty + 8 * j][tx] = in[(size_t)(k0 + ty + 8 * j) * N + n0 + tx];
    __syncthreads();
#pragma unroll
    for (int j = 0; j < 4; j++)
        out[(size_t)(n0 + ty + 8 * j) * K + k0 + tx] = __float2half_rn(s[tx][ty + 8 * j]);
}

// ---------------------------------------------------------------------------
// LayerNorm over 768. OUTH: write half (GEMM A operand) else float.
// ---------------------------------------------------------------------------
template <int OUTH>
__global__ __launch_bounds__(256) void ln_kernel(
    const float* __restrict__ in, const float* __restrict__ g,
    const float* __restrict__ b, void* __restrict__ outv)
{
    int row = blockIdx.x;
    const float* p = in + (size_t)row * 768;
    float v[3];
    float s = 0.f, ss = 0.f;
#pragma unroll
    for (int i = 0; i < 3; i++) {
        v[i] = p[threadIdx.x + i * 256];
        s += v[i]; ss += v[i] * v[i];
    }
#pragma unroll
    for (int o = 16; o > 0; o >>= 1) {
        s  += __shfl_xor_sync(0xffffffffu, s,  o);
        ss += __shfl_xor_sync(0xffffffffu, ss, o);
    }
    __shared__ float rs[8], rss[8];
    int w = threadIdx.x >> 5, lane = threadIdx.x & 31;
    if (lane == 0) { rs[w] = s; rss[w] = ss; }
    __syncthreads();
    s = 0.f; ss = 0.f;
#pragma unroll
    for (int i = 0; i < 8; i++) { s += rs[i]; ss += rss[i]; }
    float mean = s * (1.0f / 768.0f);
    float var  = ss * (1.0f / 768.0f) - mean * mean;
    float rstd = rsqrtf(var + 1e-5f);
#pragma unroll
    for (int i = 0; i < 3; i++) {
        int c = threadIdx.x + i * 256;
        float r = (v[i] - mean) * rstd * g[c] + b[c];
        if (OUTH) ((__half*)outv)[(size_t)row * 768 + c] = __float2half_rn(r);
        else      ((float*)outv)[(size_t)row * 768 + c] = r;
    }
}

// ---------------------------------------------------------------------------
// fp16 mma GEMM (R8 shape): 3-stage cp.async pipeline, frag double-buffer.
// C[M,N] = A[M,K] @ W[K,N] + bias; W transposed Wt[N,K].
// 128x256x32 CTA tile, 256 threads (8 warps 2x4), warp tile 64x64.
//   EPI=0 none | EPI=1 exact GELU | EPI=2 += res
//   OUTH: out half else float. RESH: residual half else float.
// ---------------------------------------------------------------------------
#define SM_S 40
#define GA_BUF (128 * SM_S)
#define GB_BUF (256 * SM_S)
#define GEMM_SMEM (3 * (GA_BUF + GB_BUF) * 2)

template <int EPI, int OUTH, int RESH>
__global__ __launch_bounds__(256, 1) void gemm_f16(
    const __half* __restrict__ A, const __half* __restrict__ Bt,
    const float* __restrict__ bias, const void* __restrict__ resv,
    void* __restrict__ Cv, int M, int N, int K)
{
    extern __shared__ __half smh[];
    __half* As = smh;                          // [3][128][SM_S]
    __half* Bs = smh + 3 * GA_BUF;             // [3][256][SM_S]

    int tid = threadIdx.x;
    int warp = tid >> 5, lane = tid & 31;
    int g = lane >> 2, t = lane & 3;
    int wm = (warp & 1) * 64, wn = (warp >> 1) * 64;
    int bm = blockIdx.y * 128, bn = blockIdx.x * 256;

    float acc[4][8][4];
#pragma unroll
    for (int i = 0; i < 4; i++)
#pragma unroll
        for (int j = 0; j < 8; j++)
#pragma unroll
            for (int q = 0; q < 4; q++) acc[i][j][q] = 0.f;

    const __half* Agb = A + (size_t)bm * K;
    const __half* Bgb = Bt + (size_t)bn * K;
    int ntile = K >> 5;

    // prologue: tiles 0, 1 -> stages 0, 1
#pragma unroll
    for (int pt = 0; pt < 2; pt++) {
        __half* Ab = As + pt * GA_BUF;
        __half* Bb = Bs + pt * GB_BUF;
        int k0 = pt * 32;
#pragma unroll
        for (int i = 0; i < 2; i++) {
            int idx = tid + i * 256; int r = idx >> 2, c = (idx & 3) * 8;
            cp16(&Ab[r * SM_S + c], Agb + (size_t)r * K + k0 + c);
        }
#pragma unroll
        for (int i = 0; i < 4; i++) {
            int idx = tid + i * 256; int r = idx >> 2, c = (idx & 3) * 8;
            cp16(&Bb[r * SM_S + c], Bgb + (size_t)r * K + k0 + c);
        }
        cp_commit();
    }

    for (int tt = 0; tt < ntile; tt++) {
        if (tt + 2 < ntile) {
            int st2 = (tt + 2) % 3;
            int k0 = (tt + 2) * 32;
            __half* Ab = As + st2 * GA_BUF;
            __half* Bb = Bs + st2 * GB_BUF;
#pragma unroll
            for (int i = 0; i < 2; i++) {
                int idx = tid + i * 256; int r = idx >> 2, c = (idx & 3) * 8;
                cp16(&Ab[r * SM_S + c], Agb + (size_t)r * K + k0 + c);
            }
#pragma unroll
            for (int i = 0; i < 4; i++) {
                int idx = tid + i * 256; int r = idx >> 2, c = (idx & 3) * 8;
                cp16(&Bb[r * SM_S + c], Bgb + (size_t)r * K + k0 + c);
            }
            cp_commit();
            cp_wait<2>();
        } else if (tt + 1 < ntile) {
            cp_wait<1>();
        } else {
            cp_wait<0>();
        }
        __syncthreads();

        int st = tt % 3;
        const __half* Abase = As + st * GA_BUF + (wm + g) * SM_S + 2 * t;
        const __half* Bbase = Bs + st * GB_BUF + (wn + g) * SM_S + 2 * t;

        unsigned a[2][4][4], b[2][8][2];
#pragma unroll
        for (int mt = 0; mt < 4; mt++) {
            const __half* p = Abase + mt * 16 * SM_S;
            a[0][mt][0] = *(const unsigned*)(p);
            a[0][mt][1] = *(const unsigned*)(p + 8 * SM_S);
            a[0][mt][2] = *(const unsigned*)(p + 8);
            a[0][mt][3] = *(const unsigned*)(p + 8 * SM_S + 8);
        }
#pragma unroll
        for (int nt = 0; nt < 8; nt++) {
            const __half* p = Bbase + nt * 8 * SM_S;
            b[0][nt][0] = *(const unsigned*)(p);
            b[0][nt][1] = *(const unsigned*)(p + 8);
        }
#pragma unroll
        for (int s = 0; s < 2; s++) {
            if (s == 0) {
#pragma unroll
                for (int mt = 0; mt < 4; mt++) {
                    const __half* p = Abase + mt * 16 * SM_S + 16;
                    a[1][mt][0] = *(const unsigned*)(p);
                    a[1][mt][1] = *(const unsigned*)(p + 8 * SM_S);
                    a[1][mt][2] = *(const unsigned*)(p + 8);
                    a[1][mt][3] = *(const unsigned*)(p + 8 * SM_S + 8);
                }
#pragma unroll
                for (int nt = 0; nt < 8; nt++) {
                    const __half* p = Bbase + nt * 8 * SM_S + 16;
                    b[1][nt][0] = *(const unsigned*)(p);
                    b[1][nt][1] = *(const unsigned*)(p + 8);
                }
            }
#pragma unroll
            for (int mt = 0; mt < 4; mt++)
#pragma unroll
                for (int nt = 0; nt < 8; nt++)
                    mma16(acc[mt][nt], a[s][mt], b[s][nt]);
        }
        __syncthreads();
    }

    // epilogue
#pragma unroll
    for (int mt = 0; mt < 4; mt++) {
        int r0 = bm + wm + mt * 16 + g;
        int r1 = r0 + 8;
#pragma unroll
        for (int nt = 0; nt < 8; nt++) {
            int col = bn + wn + nt * 8 + 2 * t;
            float b0 = bias[col], b1 = bias[col + 1];
            float v0 = acc[mt][nt][0] + b0, v1 = acc[mt][nt][1] + b1;
            float v2 = acc[mt][nt][2] + b0, v3 = acc[mt][nt][3] + b1;
            if (EPI == 1) {
                v0 = 0.5f * v0 * (1.0f + erff(v0 * 0.70710678118654752f));
                v1 = 0.5f * v1 * (1.0f + erff(v1 * 0.70710678118654752f));
                v2 = 0.5f * v2 * (1.0f + erff(v2 * 0.70710678118654752f));
                v3 = 0.5f * v3 * (1.0f + erff(v3 * 0.70710678118654752f));
            }
            if (EPI == 2) {
                if (RESH) {
                    const __half* rh = (const __half*)resv;
                    float2 ra = __half22float2(*(const __half2*)(rh + (size_t)r0 * N + col));
                    float2 rb = __half22float2(*(const __half2*)(rh + (size_t)r1 * N + col));
                    v0 += ra.x; v1 += ra.y; v2 += rb.x; v3 += rb.y;
                } else {
                    const float* rf = (const float*)resv;
                    float2 ra = *(const float2*)(rf + (size_t)r0 * N + col);
                    float2 rb = *(const float2*)(rf + (size_t)r1 * N + col);
                    v0 += ra.x; v1 += ra.y; v2 += rb.x; v3 += rb.y;
                }
            }
            if (OUTH) {
                __half* Ch = (__half*)Cv;
                *(__half2*)(Ch + (size_t)r0 * N + col) = __floats2half2_rn(v0, v1);
                *(__half2*)(Ch + (size_t)r1 * N + col) = __floats2half2_rn(v2, v3);
            } else {
                float* Cf = (float*)Cv;
                *(float2*)(Cf + (size_t)r0 * N + col) = make_float2(v0, v1);
                *(float2*)(Cf + (size_t)r1 * N + col) = make_float2(v2, v3);
            }
        }
    }
}

// ---------------------------------------------------------------------------
// Flash attention fp16 v5. Br=128, Bc=64, 128 threads (4 warps, 32 q-rows).
// Softmax in log2 domain: Q prescaled by 0.125*log2(e); ex2.approx only.
// P in registers (C-frag == A-frag layout). Hoisted ldmatrix bases.
// cp.async double-buffered K/V, 1 syncthreads per iteration.
// qkv half [T, 2304]: Q +0, K +768, V +1536 (head h: +h*64).
// ---------------------------------------------------------------------------
#define AT_S 72
#define ATT_SMEM ((128 + 4 * 64) * AT_S * 2)

__global__ __launch_bounds__(128, 2) void attn_f16(
    const __half* __restrict__ qkv, __half* __restrict__ ctx)
{
    extern __shared__ __half smh[];
    __half* Qs = smh;                         // Q [128][AT_S]
    __half* KV = smh + 128 * AT_S;            // [2 stages][K 64 | V 64][AT_S]

    int tid = threadIdx.x, warp = tid >> 5, lane = tid & 31;
    int g = lane >> 2, t = lane & 3;
    int bh = blockIdx.y, b = bh / 12, h = bh % 12;
    size_t base = (size_t)b * 1024 * 2304 + h * 64;
    int q0 = blockIdx.x * 128;

    // issue K/V tile 0 -> stage 0 first (hide latency under Q load)
    {
        __half* kb = KV;
        __half* vb = KV + 64 * AT_S;
        const __half* kp = qkv + base + 768;
#pragma unroll
        for (int i = 0; i < 4; i++) {
            int idx = tid + i * 128;
            int r = idx >> 3, c = (idx & 7) * 8;
            cp16(&kb[r * AT_S + c], kp + (size_t)r * 2304 + c);
            cp16(&vb[r * AT_S + c], kp + (size_t)r * 2304 + 768 + c);
        }
        cp_commit();
    }

    // load Q [128 x 64], scaled by 0.125*log2(e) -> scores in log2 domain
    __half2 s2 = __floats2half2_rn(0.18033688011112042f, 0.18033688011112042f);
#pragma unroll
    for (int i = 0; i < 8; i++) {
        int idx = tid + i * 128;
        int r = idx >> 3, c = (idx & 7) * 8;
        uint4 u = *(const uint4*)(qkv + base + (size_t)(q0 + r) * 2304 + c);
        __half2* hp = (__half2*)&u;
        hp[0] = __hmul2(hp[0], s2); hp[1] = __hmul2(hp[1], s2);
        hp[2] = __hmul2(hp[2], s2); hp[3] = __hmul2(hp[3], s2);
        *(uint4*)&Qs[r * AT_S + c] = u;
    }
    __syncthreads();

    // Q fragments in regs for whole kernel: 2 m-frags (rows warp*32 + mf*16)
    unsigned qa[2][4][4];
#pragma unroll
    for (int mf = 0; mf < 2; mf++) {
        const __half* p0 = &Qs[(warp * 32 + mf * 16 + g) * AT_S + 2 * t];
#pragma unroll
        for (int s = 0; s < 4; s++) {
            qa[mf][s][0] = *(const unsigned*)(p0 + 16 * s);
            qa[mf][s][1] = *(const unsigned*)(p0 + 16 * s + 8 * AT_S);
            qa[mf][s][2] = *(const unsigned*)(p0 + 16 * s + 8);
            qa[mf][s][3] = *(const unsigned*)(p0 + 16 * s + 8 * AT_S + 8);
        }
    }

    float o[2][8][4];
#pragma unroll
    for (int mf = 0; mf < 2; mf++)
#pragma unroll
        for (int i = 0; i < 8; i++)
#pragma unroll
            for (int j = 0; j < 4; j++) o[mf][i][j] = 0.f;
    float mrow[2][2] = {{-1e30f, -1e30f}, {-1e30f, -1e30f}};
    float lrow[2][2] = {{0.f, 0.f}, {0.f, 0.f}};

    // ldmatrix lane maps + hoisted per-stage base addresses
    int mid = lane >> 3, row8 = lane & 7;
    int bk_off = ((mid >> 1) ? 8 : 0) + row8;   // K B-frag key offset
    int bc_off = (mid & 1) * 8;                 // K B-frag k-col offset
    int lm_row = (mid & 1) * 8 + row8;          // V trans map
    int lm_col = (mid >> 1) * 8;
    uint32_t kv_smem = (uint32_t)__cvta_generic_to_shared(KV);
    uint32_t kbase[2], vbase[2];
#pragma unroll
    for (int bfi = 0; bfi < 2; bfi++) {
        uint32_t ks = kv_smem + bfi * (2 * 64 * AT_S) * 2;
        kbase[bfi] = ks + (bk_off * AT_S + bc_off) * 2;
        vbase[bfi] = ks + 64 * AT_S * 2 + (lm_row * AT_S + lm_col) * 2;
    }

    for (int kt = 0; kt < 16; kt++) {
        cp_wait<0>();
        __syncthreads();

        // issue tile kt+1
        if (kt + 1 < 16) {
            int nb = (kt + 1) & 1;
            __half* kb = KV + nb * (2 * 64 * AT_S);
            __half* vb = kb + 64 * AT_S;
            const __half* kp = qkv + base + (size_t)((kt + 1) * 64) * 2304 + 768;
#pragma unroll
            for (int i = 0; i < 4; i++) {
                int idx = tid + i * 128;
                int r = idx >> 3, c = (idx & 7) * 8;
                cp16(&kb[r * AT_S + c], kp + (size_t)r * 2304 + c);
                cp16(&vb[r * AT_S + c], kp + (size_t)r * 2304 + 768 + c);
            }
            cp_commit();
        }

        int buf = kt & 1;
        uint32_t kb0 = kbase[buf], vb0 = vbase[buf];

        // S = Q K^T (log2-domain scores); K B-frags shared across both m-frags
        float sc[2][8][4];
#pragma unroll
        for (int mf = 0; mf < 2; mf++)
#pragma unroll
            for (int i = 0; i < 8; i++)
#pragma unroll
                for (int j = 0; j < 4; j++) sc[mf][i][j] = 0.f;
#pragma unroll
        for (int s = 0; s < 4; s++) {
#pragma unroll
            for (int np = 0; np < 4; np++) {
                uint32_t addr = kb0 + (np * 16 * AT_S + 16 * s) * 2;
                unsigned r0, r1, r2, r3;
                ldsm4(r0, r1, r2, r3, addr);
                unsigned b0[2] = {r0, r1}, b1[2] = {r2, r3};
#pragma unroll
                for (int mf = 0; mf < 2; mf++) {
                    mma16(sc[mf][np * 2 + 0], qa[mf][s], b0);
                    mma16(sc[mf][np * 2 + 1], qa[mf][s], b1);
                }
            }
        }

        // online softmax per m-frag (log2 domain, single-MUFU ex2); sc <- P
#pragma unroll
        for (int mf = 0; mf < 2; mf++) {
            float mx0 = -1e30f, mx1 = -1e30f;
#pragma unroll
            for (int nt = 0; nt < 8; nt++) {
                mx0 = fmaxf(mx0, fmaxf(sc[mf][nt][0], sc[mf][nt][1]));
                mx1 = fmaxf(mx1, fmaxf(sc[mf][nt][2], sc[mf][nt][3]));
            }
            mx0 = fmaxf(mx0, __shfl_xor_sync(0xffffffffu, mx0, 1));
            mx0 = fmaxf(mx0, __shfl_xor_sync(0xffffffffu, mx0, 2));
            mx1 = fmaxf(mx1, __shfl_xor_sync(0xffffffffu, mx1, 1));
            mx1 = fmaxf(mx1, __shfl_xor_sync(0xffffffffu, mx1, 2));
            float nm0 = fmaxf(mrow[mf][0], mx0), nm1 = fmaxf(mrow[mf][1], mx1);
            float al0 = ex2(mrow[mf][0] - nm0), al1 = ex2(mrow[mf][1] - nm1);
            float ps0 = 0.f, ps1 = 0.f;
#pragma unroll
            for (int nt = 0; nt < 8; nt++) {
                float p0 = ex2(sc[mf][nt][0] - nm0);
                float p1 = ex2(sc[mf][nt][1] - nm0);
                float p2 = ex2(sc[mf][nt][2] - nm1);
                float p3 = ex2(sc[mf][nt][3] - nm1);
                ps0 += p0 + p1; ps1 += p2 + p3;
                sc[mf][nt][0] = p0; sc[mf][nt][1] = p1;
                sc[mf][nt][2] = p2; sc[mf][nt][3] = p3;
            }
            ps0 += __shfl_xor_sync(0xffffffffu, ps0, 1);
            ps0 += __shfl_xor_sync(0xffffffffu, ps0, 2);
            ps1 += __shfl_xor_sync(0xffffffffu, ps1, 1);
            ps1 += __shfl_xor_sync(0xffffffffu, ps1, 2);
            lrow[mf][0] = lrow[mf][0] * al0 + ps0;
            lrow[mf][1] = lrow[mf][1] * al1 + ps1;
            mrow[mf][0] = nm0; mrow[mf][1] = nm1;
#pragma unroll
            for (int nt = 0; nt < 8; nt++) {
                o[mf][nt][0] *= al0; o[mf][nt][1] *= al0;
                o[mf][nt][2] *= al1; o[mf][nt][3] *= al1;
            }
        }

        // O += P @ V ; P A-frags from registers, V via ldmatrix.x4.trans
#pragma unroll
        for (int s = 0; s < 4; s++) {
            unsigned pa[2][4];
#pragma unroll
            for (int mf = 0; mf < 2; mf++) {
                pa[mf][0] = pack2(sc[mf][2 * s][0], sc[mf][2 * s][1]);
                pa[mf][1] = pack2(sc[mf][2 * s][2], sc[mf][2 * s][3]);
                pa[mf][2] = pack2(sc[mf][2 * s + 1][0], sc[mf][2 * s + 1][1]);
                pa[mf][3] = pack2(sc[mf][2 * s + 1][2], sc[mf][2 * s + 1][3]);
            }
#pragma unroll
            for (int nt2 = 0; nt2 < 4; nt2++) {
                uint32_t addr = vb0 + (16 * s * AT_S + nt2 * 16) * 2;
                unsigned r0, r1, r2, r3;
                ldsm4t(r0, r1, r2, r3, addr);
                unsigned b0[2] = {r0, r1}, b1[2] = {r2, r3};
#pragma unroll
                for (int mf = 0; mf < 2; mf++) {
                    mma16(o[mf][nt2 * 2 + 0], pa[mf], b0);
                    mma16(o[mf][nt2 * 2 + 1], pa[mf], b1);
                }
            }
        }
        // no trailing sync: next iteration's barrier covers buffer reuse
    }

    __half* outb = ctx + (size_t)(b * 1024) * 768 + h * 64;
#pragma unroll
    for (int mf = 0; mf < 2; mf++) {
        float i0 = 1.0f / lrow[mf][0], i1 = 1.0f / lrow[mf][1];
        int row0 = q0 + warp * 32 + mf * 16 + g;
#pragma unroll
        for (int nt = 0; nt < 8; nt++) {
            int col = nt * 8 + 2 * t;
            *(__half2*)(outb + (size_t)row0 * 768 + col) =
                __floats2half2_rn(o[mf][nt][0] * i0, o[mf][nt][1] * i0);
            *(__half2*)(outb + (size_t)(row0 + 8) * 768 + col) =
                __floats2half2_rn(o[mf][nt][2] * i1, o[mf][nt][3] * i1);
        }
    }
}

// ---------------------------------------------------------------------------
// Host launch (graph-capturable)
// ---------------------------------------------------------------------------
extern "C" void kernel_launch(void* const* d_in, const int* in_sizes, int n_in,
                              void* d_out, int out_size)
{
    const float* x      = (const float*)d_in[0];
    const float* ln1_g  = (const float*)d_in[1];
    const float* ln1_b  = (const float*)d_in[2];
    const float* qkv_w  = (const float*)d_in[3];
    const float* qkv_b  = (const float*)d_in[4];
    const float* proj_w = (const float*)d_in[5];
    const float* proj_b = (const float*)d_in[6];
    const float* ln2_g  = (const float*)d_in[7];
    const float* ln2_b  = (const float*)d_in[8];
    const float* fc1_w  = (const float*)d_in[9];
    const float* fc1_b  = (const float*)d_in[10];
    const float* fc2_w  = (const float*)d_in[11];
    const float* fc2_b  = (const float*)d_in[12];
    const float* ln3_g  = (const float*)d_in[13];
    const float* ln3_b  = (const float*)d_in[14];
    float* out = (float*)d_out;

    __half *xn1, *qkv, *ctx, *ffin, *hid, *wq, *wp, *w1, *w2;
    float *x2, *x3;
    cudaGetSymbolAddress((void**)&xn1,  g_xn1);
    cudaGetSymbolAddress((void**)&qkv,  g_qkv);
    cudaGetSymbolAddress((void**)&ctx,  g_ctx);
    cudaGetSymbolAddress((void**)&x2,   g_x2);
    cudaGetSymbolAddress((void**)&ffin, g_ffin);
    cudaGetSymbolAddress((void**)&hid,  g_hid);
    cudaGetSymbolAddress((void**)&x3,   g_x3);
    cudaGetSymbolAddress((void**)&wq,   g_wq);
    cudaGetSymbolAddress((void**)&wp,   g_wp);
    cudaGetSymbolAddress((void**)&w1,   g_w1);
    cudaGetSymbolAddress((void**)&w2,   g_w2);

    cudaFuncSetAttribute(gemm_f16<0,1,0>, cudaFuncAttributeMaxDynamicSharedMemorySize, GEMM_SMEM);
    cudaFuncSetAttribute(gemm_f16<1,1,0>, cudaFuncAttributeMaxDynamicSharedMemorySize, GEMM_SMEM);
    cudaFuncSetAttribute(gemm_f16<2,0,0>, cudaFuncAttributeMaxDynamicSharedMemorySize, GEMM_SMEM);
    cudaFuncSetAttribute(gemm_f16<2,0,1>, cudaFuncAttributeMaxDynamicSharedMemorySize, GEMM_SMEM);
    cudaFuncSetAttribute(attn_f16, cudaFuncAttributeMaxDynamicSharedMemorySize, ATT_SMEM);

    const int T = T_TOK;

    // fused weight transpose + fp16 round (one launch)
    transpose4<<<6912, 256>>>(qkv_w, wq, proj_w, wp, fc1_w, w1, fc2_w, w2);

    // 1) xn1 = LN1(x) [half]
    ln_kernel<1><<<T, 256>>>(x, ln1_g, ln1_b, xn1);
    // 2) qkv = xn1 @ qkv_w + qkv_b [half]  (128x256 tiles)
    gemm_f16<0,1,0><<<dim3(9, 128), 256, GEMM_SMEM>>>(xn1, wq, qkv_b, nullptr, qkv, T, 2304, 768);
    // 3) ctx = attention(qkv) [half]
    attn_f16<<<dim3(8, 192), 128, ATT_SMEM>>>(qkv, ctx);
    // 4) x2 = x + ctx @ proj_w + proj_b [float]
    gemm_f16<2,0,0><<<dim3(3, 128), 256, GEMM_SMEM>>>(ctx, wp, proj_b, x, x2, T, 768, 768);
    // 5) ffin = LN2(x2) [half]
    ln_kernel<1><<<T, 256>>>(x2, ln2_g, ln2_b, ffin);
    // 6) hid = gelu(ffin @ fc1_w + fc1_b) [half]
    gemm_f16<1,1,0><<<dim3(12, 128), 256, GEMM_SMEM>>>(ffin, w1, fc1_b, nullptr, hid, T, 3072, 768);
    // 7) x3 = ffin + hid @ fc2_w + fc2_b [float] (residual from NORMALIZED tensor)
    gemm_f16<2,0,1><<<dim3(3, 128), 256, GEMM_SMEM>>>(hid, w2, fc2_b, ffin, x3, T, 768, 3072);
    // 8) out = LN3(x3)
    ln_kernel<0><<<T, 256>>>(x3, ln3_g, ln3_b, out);
}